// round 16
// baseline (speedup 1.0000x reference)
#include <cuda_runtime.h>
#include <cstdint>

#define NN 50000
#define EE 600000
#define FF 128
#define RR 4
#define RN (RR * NN)               // 200000 segments
#define NBLK ((RN + 1023) / 1024)  // 196 scan blocks
#define NT 782                     // row tiles of 64
#define ROWS (NT * 64)             // 50048 padded rows

// ---------------- scratch (static device globals; no allocation) ----------------
__device__ __align__(16) float g_h[(size_t)RR * NN * FF];
__device__ float g_sum[RR * FF];
__device__ float g_sumsq[RR * FF];
__device__ int g_cnt[RN];
__device__ int g_off[RN];
__device__ int g_bsum[256];
__device__ int g_bscan[256];
__device__ int g_cur[RN];
__device__ int g_srcbuf[EE];
// gathered + bf16-split A tiles: per (r, tile): Ah[4096 u32] then Al[4096 u32]
__device__ __align__(16) unsigned g_ab[(size_t)RR * NT * 8192u];
// 9 weight matrices, each {hi 8192 u32, lo 8192 u32}, [n][k] bf16-pair swizzled
__device__ __align__(16) unsigned g_wb[9u * 16384u];

// ---------------- helpers ---------------------------------------------------------
__device__ __forceinline__ void split2(float a0, float a1, unsigned& hi, unsigned& lo) {
    asm("cvt.rn.bf16x2.f32 %0, %1, %2;" : "=r"(hi) : "f"(a1), "f"(a0));
    float h0 = __uint_as_float(hi << 16);
    float h1 = __uint_as_float(hi & 0xffff0000u);
    float l0 = a0 - h0, l1 = a1 - h1;
    asm("cvt.rn.bf16x2.f32 %0, %1, %2;" : "=r"(lo) : "f"(l1), "f"(l0));
}

__device__ __forceinline__ uint32_t smem_u32(const void* p) {
    uint32_t a;
    asm("{ .reg .u64 t; cvta.to.shared.u64 t, %1; cvt.u32.u64 %0, t; }" : "=r"(a) : "l"(p));
    return a;
}

// no volatile on LDSM/MMA — lets ptxas software-pipeline across iterations.
#define MMA_BF16(c, a, b)                                                          \
    asm("mma.sync.aligned.m16n8k16.row.col.f32.bf16.bf16.f32 "                     \
        "{%0,%1,%2,%3}, {%4,%5,%6,%7}, {%8,%9}, {%0,%1,%2,%3};"                    \
        : "+f"((c)[0]), "+f"((c)[1]), "+f"((c)[2]), "+f"((c)[3])                   \
        : "r"((a)[0]), "r"((a)[1]), "r"((a)[2]), "r"((a)[3]), "r"((b)[0]),         \
          "r"((b)[1]))

#define LDSM4(r, a)                                                                \
    asm("ldmatrix.sync.aligned.m8n8.x4.shared.b16 {%0,%1,%2,%3}, [%4];"            \
        : "=r"((r)[0]), "=r"((r)[1]), "=r"((r)[2]), "=r"((r)[3])                   \
        : "r"(a))

#define LDSM2(r, a)                                                                \
    asm("ldmatrix.sync.aligned.m8n8.x2.shared.b16 {%0,%1}, [%2];"                  \
        : "=r"((r)[0]), "=r"((r)[1])                                               \
        : "r"(a))

#define CP16(dst, src)                                                             \
    asm volatile("cp.async.cg.shared.global [%0], [%1], 16;" :: "r"(dst), "l"(src))
#define CP_WAIT()                                                                  \
    asm volatile("cp.async.commit_group;\n\tcp.async.wait_group 0;" ::: "memory")

// ---------------- prep + hist fused (launch 1) --------------------------------------
__device__ __forceinline__ void prep_one(const float* W, unsigned* outh, unsigned* outl,
                                         int tid) {
    for (int q = tid; q < 8192; q += 256) {
        int n = q & 127, ku = q >> 7;
        float a0 = W[(2 * ku) * FF + n];
        float a1 = W[(2 * ku + 1) * FF + n];
        unsigned hi, lo;
        split2(a0, a1, hi, lo);
        unsigned idx = n * 64 + (ku ^ ((n & 7) << 2));
        outh[idx] = hi;
        outl[idx] = lo;
    }
}

__global__ void prep_hist_kernel(const float* __restrict__ W1, const float* __restrict__ Wself,
                                 const float* __restrict__ W2, const int* __restrict__ ei,
                                 const int* __restrict__ et) {
    int b = blockIdx.x;
    if (b < 9) {
        const float* W = (b < 4) ? (W1 + b * (FF * FF))
                                 : ((b == 4) ? Wself : (W2 + (b - 5) * (FF * FF)));
        prep_one(W, g_wb + (size_t)b * 16384u, g_wb + (size_t)b * 16384u + 8192, threadIdx.x);
    } else {
        int e = (b - 9) * 256 + threadIdx.x;
        if (e < EE) {
            int s = et[e] * NN + ei[e];
            atomicAdd(&g_cnt[s], 1);
        }
    }
}

// ---------------- scan stage 1 (+ zero g_cur, zero BN stats) -------------------------
__global__ void scan1_kernel() {
    __shared__ int sh[512];
    int t = threadIdx.x;
    if (blockIdx.x == 0) {
        g_sum[t] = 0.f;
        g_sumsq[t] = 0.f;
    }
    int base = blockIdx.x * 1024;
    int i0 = base + 2 * t, i1 = i0 + 1;
    int c0 = (i0 < RN) ? g_cnt[i0] : 0;
    int c1 = (i1 < RN) ? g_cnt[i1] : 0;
    if (i0 < RN) g_cur[i0] = 0;
    if (i1 < RN) g_cur[i1] = 0;
    int s = c0 + c1;
    sh[t] = s;
    __syncthreads();
    for (int d = 1; d < 512; d <<= 1) {
        int v = (t >= d) ? sh[t - d] : 0;
        __syncthreads();
        sh[t] += v;
        __syncthreads();
    }
    int excl = sh[t] - s;
    if (i0 < RN) g_off[i0] = excl;
    if (i1 < RN) g_off[i1] = excl + c0;
    if (t == 511) g_bsum[blockIdx.x] = sh[511];
}

// ---------------- reorder (computes block-total scan inline; blk 0 persists it) ------
__global__ void reorder_kernel(const int* __restrict__ ei, const int* __restrict__ et) {
    __shared__ int sb[256];
    int t = threadIdx.x;
    int v = (t < NBLK) ? g_bsum[t] : 0;
    sb[t] = v;
    __syncthreads();
    for (int d = 1; d < 256; d <<= 1) {
        int u = (t >= d) ? sb[t - d] : 0;
        __syncthreads();
        sb[t] += u;
        __syncthreads();
    }
    int excl = sb[t] - v;
    if (blockIdx.x == 0) g_bscan[t] = excl;  // persist for gather
    __syncthreads();
    sb[t] = excl;
    __syncthreads();
    int e = blockIdx.x * blockDim.x + t;
    if (e >= EE) return;
    int s = et[e] * NN + ei[e];
    int base = g_off[s] + sb[s >> 10];
    int pos = base + atomicAdd(&g_cur[s], 1);
    g_srcbuf[pos] = ei[EE + e];
}

// ---------------- gather: g_ab[(r,row)] = bf16split(x[row] + Σ x[src]) ---------------
__global__ void gather_kernel(const float4* __restrict__ x4) {
    int w = (blockIdx.x * blockDim.x + threadIdx.x) >> 5;
    int lane = threadIdx.x & 31;
    if (w >= RR * ROWS) return;
    int r = w / ROWS, row = w % ROWS;
    float4 acc = make_float4(0.f, 0.f, 0.f, 0.f);
    if (row < NN) {
        acc = x4[(size_t)row * 32 + lane];
        int seg = r * NN + row;
        int start = g_off[seg] + g_bscan[seg >> 10];
        int cnt = g_cnt[seg];
        for (int e = 0; e < cnt; ++e) {
            int src = g_srcbuf[start + e];
            float4 v = x4[(size_t)src * 32 + lane];
            acc.x += v.x; acc.y += v.y; acc.z += v.z; acc.w += v.w;
        }
    }
    unsigned h0, l0, h1, l1;
    split2(acc.x, acc.y, h0, l0);
    split2(acc.z, acc.w, h1, l1);
    int tile = row >> 6, lrow = row & 63;
    unsigned* base = g_ab + ((size_t)(r * NT + tile)) * 8192u;
    int idx = lrow * 64 + ((lane * 2) ^ ((lrow & 7) << 2));
    base[idx] = h0; base[idx + 1] = h1;
    base[4096 + idx] = l0; base[4096 + idx + 1] = l1;
}

// ================= shared 64x128 HMMA machinery =====================================
// smem u32: Ah[0,4096) Al[4096,8192) Bh[8192,16384) Bl[16384,24576)
// gemm1 extra: red[256]@24576.  gemm2 extras: s_scale@24576, s_shift@25088, s_bias@25600.
#define SMEM1_BYTES 99328
#define SMEM2_BYTES 102912

__device__ __forceinline__ void copy_b128_async(uint32_t smb, int mat, int tid) {
    const float4* src = (const float4*)(g_wb + (size_t)mat * 16384u);
    uint32_t dst = smb + 32768u + (uint32_t)tid * 16u;
#pragma unroll
    for (int it = 0; it < 16; ++it) CP16(dst + it * 4096u, src + it * 256 + tid);
}

__device__ __forceinline__ void frag_bases128(uint32_t smb, int lane, int wm, int wn,
                                              uint32_t& arow, uint32_t& brow,
                                              uint32_t& aku0, uint32_t& bku0, uint32_t& sw) {
    arow = smb + (uint32_t)(wm + (lane & 15)) * 256u;
    brow = smb + 32768u + (uint32_t)(wn + (lane & 7)) * 256u;
    aku0 = ((uint32_t)(lane >> 4)) << 2;
    bku0 = (((uint32_t)(lane >> 3)) & 1u) << 2;
    sw = ((uint32_t)(lane & 7)) << 2;
}

__device__ __forceinline__ void mma_tile128(float (*acc)[4][4], uint32_t arow, uint32_t brow,
                                            uint32_t aku0, uint32_t bku0, uint32_t sw) {
#pragma unroll
    for (int kc = 0; kc < 8; ++kc) {
        uint32_t ak = ((aku0 + 8u * kc) ^ sw) << 2;
        uint32_t bk = ((bku0 + 8u * kc) ^ sw) << 2;
        unsigned bh[4][2], bl[4][2];
#pragma unroll
        for (int nj = 0; nj < 4; ++nj) {
            LDSM2(bh[nj], brow + nj * 2048u + bk);
            LDSM2(bl[nj], brow + 32768u + nj * 2048u + bk);
        }
#pragma unroll
        for (int mi = 0; mi < 2; ++mi) {
            unsigned ah[4], al[4];
            LDSM4(ah, arow + mi * 4096u + ak);
            LDSM4(al, arow + 16384u + mi * 4096u + ak);
#pragma unroll
            for (int nj = 0; nj < 4; ++nj) {
                MMA_BF16(acc[mi][nj], ah, bh[nj]);
                MMA_BF16(acc[mi][nj], ah, bl[nj]);
                MMA_BF16(acc[mi][nj], al, bh[nj]);
            }
        }
    }
}

// ---------------- GEMM1: per-CTA loop over 4 relations, A register-prefetch ----------
__global__ __launch_bounds__(256, 2) void gemm1_tc(const float* __restrict__ b1g) {
    extern __shared__ unsigned sm[];
    float* red = (float*)(sm + 24576);  // [0,128) sum, [128,256) sumsq
    const uint32_t smb = smem_u32(sm);
    const int tid = threadIdx.x, wid = tid >> 5, lane = tid & 31;
    const int gq = lane >> 2, tq = lane & 3;
    const int wm = (wid & 1) * 32, wn = (wid >> 1) * 32;
    const int tile = blockIdx.x, row0 = tile * 64;

    uint32_t arow, brow, aku0, bku0, sw;
    frag_bases128(smb, lane, wm, wn, arow, brow, aku0, bku0, sw);

    // prefetch rel 0 A tile (already bf16-split + swizzled in g_ab)
    uint4 pre[8];
    {
        const uint4* src = (const uint4*)(g_ab + (size_t)tile * 8192u);
#pragma unroll
        for (int it = 0; it < 8; ++it) pre[it] = src[it * 256 + tid];
    }

    for (int rel = 0; rel < RR; ++rel) {
        __syncthreads();  // prev mma/epilogue done with smem
        copy_b128_async(smb, rel, tid);
#pragma unroll
        for (int it = 0; it < 8; ++it) ((uint4*)sm)[it * 256 + tid] = pre[it];
        CP_WAIT();
        __syncthreads();

        // prefetch next rel's A while mma runs
        if (rel < RR - 1) {
            const uint4* src = (const uint4*)(g_ab + ((size_t)((rel + 1) * NT + tile)) * 8192u);
#pragma unroll
            for (int it = 0; it < 8; ++it) pre[it] = src[it * 256 + tid];
        }

        float acc[2][4][4];
#pragma unroll
        for (int mi = 0; mi < 2; ++mi)
#pragma unroll
            for (int nj = 0; nj < 4; ++nj)
#pragma unroll
                for (int c = 0; c < 4; ++c) acc[mi][nj][c] = 0.f;

        mma_tile128(acc, arow, brow, aku0, bku0, sw);

        // bias into accumulators (stats see h directly)
        const float* bias = b1g + rel * FF;
#pragma unroll
        for (int nj = 0; nj < 4; ++nj) {
            int col = wn + nj * 8 + 2 * tq;
            float bx = bias[col], by = bias[col + 1];
#pragma unroll
            for (int mi = 0; mi < 2; ++mi) {
                acc[mi][nj][0] += bx; acc[mi][nj][1] += by;
                acc[mi][nj][2] += bx; acc[mi][nj][3] += by;
            }
        }

        // store h
        float* H = g_h + (size_t)rel * (NN * FF);
#pragma unroll
        for (int mi = 0; mi < 2; ++mi) {
            int ra = row0 + wm + mi * 16 + gq;
#pragma unroll
            for (int nj = 0; nj < 4; ++nj) {
                int col = wn + nj * 8 + 2 * tq;
                if (ra < NN)
                    *(float2*)(H + (size_t)ra * FF + col) =
                        make_float2(acc[mi][nj][0], acc[mi][nj][1]);
                if (ra + 8 < NN)
                    *(float2*)(H + (size_t)(ra + 8) * FF + col) =
                        make_float2(acc[mi][nj][2], acc[mi][nj][3]);
            }
        }

        // fused BN stats (dedicated red buffer; doesn't alias A/B tiles)
        red[tid] = 0.f;
        __syncthreads();
#pragma unroll
        for (int nj = 0; nj < 4; ++nj)
#pragma unroll
            for (int par = 0; par < 2; ++par) {
                int col = wn + nj * 8 + 2 * tq + par;
                float s = 0.f, q = 0.f;
#pragma unroll
                for (int mi = 0; mi < 2; ++mi) {
                    int ra = row0 + wm + mi * 16 + gq;
                    if (ra < NN) {
                        float v = acc[mi][nj][par];
                        s += v; q = fmaf(v, v, q);
                    }
                    if (ra + 8 < NN) {
                        float v = acc[mi][nj][2 + par];
                        s += v; q = fmaf(v, v, q);
                    }
                }
                atomicAdd(&red[col], s);
                atomicAdd(&red[128 + col], q);
            }
        __syncthreads();
        if (tid < 128) {
            atomicAdd(&g_sum[rel * FF + tid], red[tid]);
            atomicAdd(&g_sumsq[rel * FF + tid], red[128 + tid]);
        }
    }
}

// ---------------- GEMM2: out = x@Wself + sum_r relu(bn(h_r))@W2[r] + bias -----------
__global__ __launch_bounds__(256, 2) void gemm2_tc(const float* __restrict__ x,
                                                   const float* __restrict__ gamma,
                                                   const float* __restrict__ beta,
                                                   const float* __restrict__ bself,
                                                   const float* __restrict__ b2g,
                                                   float* __restrict__ out) {
    extern __shared__ unsigned sm[];
    unsigned* Ah = sm;
    unsigned* Al = sm + 4096;
    float* s_scale = (float*)(sm + 24576);
    float* s_shift = (float*)(sm + 25088);
    float* s_bias  = (float*)(sm + 25600);
    const uint32_t smb = smem_u32(sm);
    const int tid = threadIdx.x, wid = tid >> 5, lane = tid & 31;
    const int gq = lane >> 2, tq = lane & 3;
    const int wm = (wid & 1) * 32, wn = (wid >> 1) * 32;
    const int row0 = blockIdx.x * 64;

    // fused BN finalize (reads gemm1's global stats)
    for (int i = tid; i < RR * FF; i += 256) {
        float inv_n = 1.0f / (float)NN;
        float mean = g_sum[i] * inv_n;
        float var = g_sumsq[i] * inv_n - mean * mean;
        if (var < 0.f) var = 0.f;
        float scv = gamma[i] * rsqrtf(var + 1e-5f);
        s_scale[i] = scv;
        s_shift[i] = beta[i] - mean * scv;
    }
    for (int i = tid; i < FF; i += 256) {
        float b = bself[i];
#pragma unroll
        for (int rr = 0; rr < RR; ++rr) b += b2g[rr * FF + i];
        s_bias[i] = b;
    }

    float acc[2][4][4];
#pragma unroll
    for (int mi = 0; mi < 2; ++mi)
#pragma unroll
        for (int nj = 0; nj < 4; ++nj)
#pragma unroll
            for (int c = 0; c < 4; ++c) acc[mi][nj][c] = 0.f;

    uint32_t arow, brow, aku0, bku0, sw;
    frag_bases128(smb, lane, wm, wn, arow, brow, aku0, bku0, sw);

    // prefetch rel=0 A (x) into registers
    float4 pre[8];
#pragma unroll
    for (int it = 0; it < 8; ++it) {
        int q = it * 256 + tid;
        int row = q >> 5, c4 = q & 31;
        int grow = row0 + row;
        pre[it] = (grow < NN) ? ((const float4*)x)[(size_t)grow * 32 + c4]
                              : make_float4(0.f, 0.f, 0.f, 0.f);
    }

    for (int rel = 0; rel < 5; ++rel) {
        __syncthreads();
        copy_b128_async(smb, 4 + rel, tid);

        const float* sc = s_scale + (rel - 1) * FF;
        const float* sf = s_shift + (rel - 1) * FF;
#pragma unroll
        for (int it = 0; it < 8; ++it) {
            int q = it * 256 + tid;
            int row = q >> 5, c4 = q & 31, k4 = c4 * 4;
            float4 v = pre[it];
            if (rel > 0) {
                v.x = fmaxf(fmaf(v.x, sc[k4 + 0], sf[k4 + 0]), 0.f);
                v.y = fmaxf(fmaf(v.y, sc[k4 + 1], sf[k4 + 1]), 0.f);
                v.z = fmaxf(fmaf(v.z, sc[k4 + 2], sf[k4 + 2]), 0.f);
                v.w = fmaxf(fmaf(v.w, sc[k4 + 3], sf[k4 + 3]), 0.f);
            }
            unsigned h0, l0, h1, l1;
            split2(v.x, v.y, h0, l0);
            split2(v.z, v.w, h1, l1);
            int idx = row * 64 + ((c4 * 2) ^ ((row & 7) << 2));
            Ah[idx] = h0; Ah[idx + 1] = h1;
            Al[idx] = l0; Al[idx + 1] = l1;
        }
        CP_WAIT();
        __syncthreads();

        if (rel < 4) {
            const float* An = g_h + (size_t)rel * (NN * FF);
#pragma unroll
            for (int it = 0; it < 8; ++it) {
                int q = it * 256 + tid;
                int row = q >> 5, c4 = q & 31;
                int grow = row0 + row;
                pre[it] = (grow < NN) ? ((const float4*)An)[(size_t)grow * 32 + c4]
                                      : make_float4(0.f, 0.f, 0.f, 0.f);
            }
        }

        mma_tile128(acc, arow, brow, aku0, bku0, sw);
    }

#pragma unroll
    for (int mi = 0; mi < 2; ++mi) {
        int ra = row0 + wm + mi * 16 + gq;
#pragma unroll
        for (int nj = 0; nj < 4; ++nj) {
            int col = wn + nj * 8 + 2 * tq;
            float bx = s_bias[col], by = s_bias[col + 1];
            if (ra < NN)
                *(float2*)(out + (size_t)ra * FF + col) =
                    make_float2(acc[mi][nj][0] + bx, acc[mi][nj][1] + by);
            if (ra + 8 < NN)
                *(float2*)(out + (size_t)(ra + 8) * FF + col) =
                    make_float2(acc[mi][nj][2] + bx, acc[mi][nj][3] + by);
        }
    }
}

// ---------------- launch ---------------------------------------------------------
extern "C" void kernel_launch(void* const* d_in, const int* in_sizes, int n_in,
                              void* d_out, int out_size) {
    const float* x     = (const float*)d_in[0];
    const int*   ei    = (const int*)d_in[1];
    const int*   et    = (const int*)d_in[2];
    const float* Wself = (const float*)d_in[3];
    const float* bself = (const float*)d_in[4];
    const float* W1    = (const float*)d_in[5];
    const float* b1    = (const float*)d_in[6];
    const float* gamma = (const float*)d_in[7];
    const float* beta  = (const float*)d_in[8];
    const float* W2    = (const float*)d_in[9];
    const float* b2    = (const float*)d_in[10];
    float* out = (float*)d_out;

    void* p_cnt = nullptr;
    cudaGetSymbolAddress(&p_cnt, g_cnt);
    cudaMemsetAsync(p_cnt, 0, RN * sizeof(int));

    cudaFuncSetAttribute(gemm1_tc, cudaFuncAttributeMaxDynamicSharedMemorySize, SMEM1_BYTES);
    cudaFuncSetAttribute(gemm2_tc, cudaFuncAttributeMaxDynamicSharedMemorySize, SMEM2_BYTES);

    prep_hist_kernel<<<9 + (EE + 255) / 256, 256>>>(W1, Wself, W2, ei, et);   // 1
    scan1_kernel<<<NBLK, 512>>>();                                            // 2
    reorder_kernel<<<(EE + 255) / 256, 256>>>(ei, et);                        // 3
    gather_kernel<<<(RR * ROWS * 32) / 256, 256>>>((const float4*)x);         // 4: profiled
    gemm1_tc<<<NT, 256, SMEM1_BYTES>>>(b1);                                   // 5
    gemm2_tc<<<NT, 256, SMEM2_BYTES>>>(x, gamma, beta, bself, b2, out);       // 6
}

// round 17
// speedup vs baseline: 1.4926x; 1.4926x over previous
#include <cuda_runtime.h>
#include <cstdint>

#define NN 50000
#define EE 600000
#define FF 128
#define RR 4
#define RN (RR * NN)               // 200000 segments
#define NBLK ((RN + 1023) / 1024)  // 196 scan blocks
#define NT 782                     // row tiles of 64
#define ROWS (NT * 64)             // 50048 padded rows

// ---------------- scratch (static device globals; no allocation) ----------------
__device__ __align__(16) float g_h[(size_t)RR * NN * FF];
__device__ float g_sum[RR * FF];
__device__ float g_sumsq[RR * FF];
__device__ int g_cnt[RN];
__device__ int g_off[RN];
__device__ int g_bsum[256];
__device__ int g_bscan[256];
__device__ int g_cur[RN];
__device__ int g_srcbuf[EE];
// gathered + bf16-split A tiles: per (r, tile): Ah[4096 u32] then Al[4096 u32]
__device__ __align__(16) unsigned g_ab[(size_t)RR * NT * 8192u];
// 9 weight matrices, each {hi 8192 u32, lo 8192 u32}, [n][k] bf16-pair swizzled
__device__ __align__(16) unsigned g_wb[9u * 16384u];

// ---------------- helpers ---------------------------------------------------------
__device__ __forceinline__ void split2(float a0, float a1, unsigned& hi, unsigned& lo) {
    asm("cvt.rn.bf16x2.f32 %0, %1, %2;" : "=r"(hi) : "f"(a1), "f"(a0));
    float h0 = __uint_as_float(hi << 16);
    float h1 = __uint_as_float(hi & 0xffff0000u);
    float l0 = a0 - h0, l1 = a1 - h1;
    asm("cvt.rn.bf16x2.f32 %0, %1, %2;" : "=r"(lo) : "f"(l1), "f"(l0));
}

__device__ __forceinline__ uint32_t smem_u32(const void* p) {
    uint32_t a;
    asm("{ .reg .u64 t; cvta.to.shared.u64 t, %1; cvt.u32.u64 %0, t; }" : "=r"(a) : "l"(p));
    return a;
}

// no volatile on LDSM/MMA — lets ptxas software-pipeline across iterations.
#define MMA_BF16(c, a, b)                                                          \
    asm("mma.sync.aligned.m16n8k16.row.col.f32.bf16.bf16.f32 "                     \
        "{%0,%1,%2,%3}, {%4,%5,%6,%7}, {%8,%9}, {%0,%1,%2,%3};"                    \
        : "+f"((c)[0]), "+f"((c)[1]), "+f"((c)[2]), "+f"((c)[3])                   \
        : "r"((a)[0]), "r"((a)[1]), "r"((a)[2]), "r"((a)[3]), "r"((b)[0]),         \
          "r"((b)[1]))

#define MMA_BF16_P(c, a0, a1, a2, a3, b0, b1)                                      \
    asm("mma.sync.aligned.m16n8k16.row.col.f32.bf16.bf16.f32 "                     \
        "{%0,%1,%2,%3}, {%4,%5,%6,%7}, {%8,%9}, {%0,%1,%2,%3};"                    \
        : "+f"((c)[0]), "+f"((c)[1]), "+f"((c)[2]), "+f"((c)[3])                   \
        : "r"(a0), "r"(a1), "r"(a2), "r"(a3), "r"(b0), "r"(b1))

#define LDSM4(r, a)                                                                \
    asm("ldmatrix.sync.aligned.m8n8.x4.shared.b16 {%0,%1,%2,%3}, [%4];"            \
        : "=r"((r)[0]), "=r"((r)[1]), "=r"((r)[2]), "=r"((r)[3])                   \
        : "r"(a))

#define LDSM2(r, a)                                                                \
    asm("ldmatrix.sync.aligned.m8n8.x2.shared.b16 {%0,%1}, [%2];"                  \
        : "=r"((r)[0]), "=r"((r)[1])                                               \
        : "r"(a))

#define CP16(dst, src)                                                             \
    asm volatile("cp.async.cg.shared.global [%0], [%1], 16;" :: "r"(dst), "l"(src))
#define CP_WAIT()                                                                  \
    asm volatile("cp.async.commit_group;\n\tcp.async.wait_group 0;" ::: "memory")

// ---------------- prep + hist fused (launch 1) --------------------------------------
__device__ __forceinline__ void prep_one(const float* W, unsigned* outh, unsigned* outl,
                                         int tid) {
    for (int q = tid; q < 8192; q += 256) {
        int n = q & 127, ku = q >> 7;
        float a0 = W[(2 * ku) * FF + n];
        float a1 = W[(2 * ku + 1) * FF + n];
        unsigned hi, lo;
        split2(a0, a1, hi, lo);
        unsigned idx = n * 64 + (ku ^ ((n & 7) << 2));
        outh[idx] = hi;
        outl[idx] = lo;
    }
}

__global__ void prep_hist_kernel(const float* __restrict__ W1, const float* __restrict__ Wself,
                                 const float* __restrict__ W2, const int* __restrict__ ei,
                                 const int* __restrict__ et) {
    int b = blockIdx.x;
    if (b < 9) {
        const float* W = (b < 4) ? (W1 + b * (FF * FF))
                                 : ((b == 4) ? Wself : (W2 + (b - 5) * (FF * FF)));
        prep_one(W, g_wb + (size_t)b * 16384u, g_wb + (size_t)b * 16384u + 8192, threadIdx.x);
    } else {
        int e = (b - 9) * 256 + threadIdx.x;
        if (e < EE) {
            int s = et[e] * NN + ei[e];
            atomicAdd(&g_cnt[s], 1);
        }
    }
}

// ---------------- scan stage 1 (+ zero g_cur, zero BN stats) -------------------------
__global__ void scan1_kernel() {
    __shared__ int sh[512];
    int t = threadIdx.x;
    if (blockIdx.x == 0) {
        g_sum[t] = 0.f;
        g_sumsq[t] = 0.f;
    }
    int base = blockIdx.x * 1024;
    int i0 = base + 2 * t, i1 = i0 + 1;
    int c0 = (i0 < RN) ? g_cnt[i0] : 0;
    int c1 = (i1 < RN) ? g_cnt[i1] : 0;
    if (i0 < RN) g_cur[i0] = 0;
    if (i1 < RN) g_cur[i1] = 0;
    int s = c0 + c1;
    sh[t] = s;
    __syncthreads();
    for (int d = 1; d < 512; d <<= 1) {
        int v = (t >= d) ? sh[t - d] : 0;
        __syncthreads();
        sh[t] += v;
        __syncthreads();
    }
    int excl = sh[t] - s;
    if (i0 < RN) g_off[i0] = excl;
    if (i1 < RN) g_off[i1] = excl + c0;
    if (t == 511) g_bsum[blockIdx.x] = sh[511];
}

// ---------------- reorder (computes block-total scan inline; blk 0 persists it) ------
__global__ void reorder_kernel(const int* __restrict__ ei, const int* __restrict__ et) {
    __shared__ int sb[256];
    int t = threadIdx.x;
    int v = (t < NBLK) ? g_bsum[t] : 0;
    sb[t] = v;
    __syncthreads();
    for (int d = 1; d < 256; d <<= 1) {
        int u = (t >= d) ? sb[t - d] : 0;
        __syncthreads();
        sb[t] += u;
        __syncthreads();
    }
    int excl = sb[t] - v;
    if (blockIdx.x == 0) g_bscan[t] = excl;  // persist for gather
    __syncthreads();
    sb[t] = excl;
    __syncthreads();
    int e = blockIdx.x * blockDim.x + t;
    if (e >= EE) return;
    int s = et[e] * NN + ei[e];
    int base = g_off[s] + sb[s >> 10];
    int pos = base + atomicAdd(&g_cur[s], 1);
    g_srcbuf[pos] = ei[EE + e];
}

// ---------------- gather: g_ab[(r,row)] = bf16split(x[row] + Σ x[src]) ---------------
__global__ void gather_kernel(const float4* __restrict__ x4) {
    int w = (blockIdx.x * blockDim.x + threadIdx.x) >> 5;
    int lane = threadIdx.x & 31;
    if (w >= RR * ROWS) return;
    int r = w / ROWS, row = w % ROWS;
    float4 acc = make_float4(0.f, 0.f, 0.f, 0.f);
    if (row < NN) {
        acc = x4[(size_t)row * 32 + lane];
        int seg = r * NN + row;
        int start = g_off[seg] + g_bscan[seg >> 10];
        int cnt = g_cnt[seg];
        for (int e = 0; e < cnt; ++e) {
            int src = g_srcbuf[start + e];
            float4 v = x4[(size_t)src * 32 + lane];
            acc.x += v.x; acc.y += v.y; acc.z += v.z; acc.w += v.w;
        }
    }
    unsigned h0, l0, h1, l1;
    split2(acc.x, acc.y, h0, l0);
    split2(acc.z, acc.w, h1, l1);
    int tile = row >> 6, lrow = row & 63;
    unsigned* base = g_ab + ((size_t)(r * NT + tile)) * 8192u;
    int idx = lrow * 64 + ((lane * 2) ^ ((lrow & 7) << 2));  // always even -> 8B aligned
    *(uint2*)(base + idx) = make_uint2(h0, h1);
    *(uint2*)(base + 4096 + idx) = make_uint2(l0, l1);
}

// ================= GEMM1: 64x64 tiles, 3 CTAs/SM ====================================
// smem u32 units: Ah[0,4096) Al[4096,8192) Bh[8192,12288) Bl[12288,16384)
#define SMEM1_BYTES 65536

__device__ __forceinline__ void copy_b64_async(uint32_t smb, int mat, int h, int tid) {
    const float4* srch = (const float4*)(g_wb + (size_t)mat * 16384u + (size_t)h * 4096u);
    const float4* srcl = srch + 2048;  // +8192 u32
    uint32_t dst = smb + 32768u + (uint32_t)tid * 16u;
#pragma unroll
    for (int it = 0; it < 4; ++it) CP16(dst + it * 4096u, srch + it * 256 + tid);
#pragma unroll
    for (int it = 0; it < 4; ++it) CP16(dst + 16384u + it * 4096u, srcl + it * 256 + tid);
}

__device__ __forceinline__ void copy_a_async(uint32_t smb, int r, int tile, int tid) {
    const float4* src = (const float4*)(g_ab + ((size_t)(r * NT + tile)) * 8192u);
    uint32_t dst = smb + (uint32_t)tid * 16u;
#pragma unroll
    for (int it = 0; it < 8; ++it) CP16(dst + it * 4096u, src + it * 256 + tid);
}

// per-lane frag bases for 64x64 tile (B 2-kc LDSM4 batching)
__device__ __forceinline__ void frag_bases64(uint32_t smb, int lane, int wm, int wn,
                                             uint32_t& arow, uint32_t& brow,
                                             uint32_t& aku0, uint32_t& bku0, uint32_t& sw) {
    arow = smb + (uint32_t)(wm + (lane & 15)) * 256u;
    brow = smb + 32768u + (uint32_t)(wn + (lane & 7)) * 256u;
    aku0 = ((uint32_t)(lane >> 4)) << 2;
    bku0 = (((uint32_t)(lane >> 3)) & 1u) * 4u + (((uint32_t)(lane >> 4)) & 1u) * 8u;
    sw = ((uint32_t)(lane & 7)) << 2;
}

__device__ __forceinline__ void mma_tile64(float (*acc)[2][4], uint32_t arow, uint32_t brow,
                                           uint32_t aku0, uint32_t bku0, uint32_t sw) {
#pragma unroll
    for (int kp = 0; kp < 4; ++kp) {
        uint32_t bk = ((bku0 + 16u * kp) ^ sw) << 2;
        uint32_t ak0 = ((aku0 + 16u * kp) ^ sw) << 2;
        uint32_t ak1 = ((aku0 + 16u * kp + 8u) ^ sw) << 2;
        unsigned bh[2][4], bl[2][4];
#pragma unroll
        for (int nj = 0; nj < 2; ++nj) {
            LDSM4(bh[nj], brow + nj * 2048u + bk);
            LDSM4(bl[nj], brow + 16384u + nj * 2048u + bk);
        }
#pragma unroll
        for (int mi = 0; mi < 2; ++mi) {
            unsigned ah0[4], al0[4], ah1[4], al1[4];
            LDSM4(ah0, arow + mi * 4096u + ak0);
            LDSM4(al0, arow + 16384u + mi * 4096u + ak0);
            LDSM4(ah1, arow + mi * 4096u + ak1);
            LDSM4(al1, arow + 16384u + mi * 4096u + ak1);
#pragma unroll
            for (int nj = 0; nj < 2; ++nj) {
                MMA_BF16_P(acc[mi][nj], ah0[0], ah0[1], ah0[2], ah0[3], bh[nj][0], bh[nj][1]);
                MMA_BF16_P(acc[mi][nj], ah0[0], ah0[1], ah0[2], ah0[3], bl[nj][0], bl[nj][1]);
                MMA_BF16_P(acc[mi][nj], al0[0], al0[1], al0[2], al0[3], bh[nj][0], bh[nj][1]);
                MMA_BF16_P(acc[mi][nj], ah1[0], ah1[1], ah1[2], ah1[3], bh[nj][2], bh[nj][3]);
                MMA_BF16_P(acc[mi][nj], ah1[0], ah1[1], ah1[2], ah1[3], bl[nj][2], bl[nj][3]);
                MMA_BF16_P(acc[mi][nj], al1[0], al1[1], al1[2], al1[3], bh[nj][2], bh[nj][3]);
            }
        }
    }
}

// grid (NT, 8): blockIdx.y = r*2 + nhalf
__global__ __launch_bounds__(256, 3) void gemm1_tc(const float* __restrict__ b1g) {
    extern __shared__ unsigned sm[];
    const uint32_t smb = smem_u32(sm);
    const int tid = threadIdx.x, wid = tid >> 5, lane = tid & 31;
    const int gq = lane >> 2, tq = lane & 3;
    const int wm = (wid & 1) * 32, wn = (wid >> 1) * 16;
    const int r = blockIdx.y >> 1, nh = blockIdx.y & 1;
    const int row0 = blockIdx.x * 64;

    copy_a_async(smb, r, blockIdx.x, tid);
    copy_b64_async(smb, r, nh, tid);
    CP_WAIT();
    __syncthreads();

    float acc[2][2][4];
#pragma unroll
    for (int mi = 0; mi < 2; ++mi)
#pragma unroll
        for (int nj = 0; nj < 2; ++nj)
#pragma unroll
            for (int c = 0; c < 4; ++c) acc[mi][nj][c] = 0.f;

    uint32_t arow, brow, aku0, bku0, sw;
    frag_bases64(smb, lane, wm, wn, arow, brow, aku0, bku0, sw);
    mma_tile64(acc, arow, brow, aku0, bku0, sw);

    // add bias into accumulators (stats see h directly)
    const float* bias = b1g + r * FF + nh * 64;
#pragma unroll
    for (int nj = 0; nj < 2; ++nj) {
        int col = wn + nj * 8 + 2 * tq;
        float bx = bias[col], by = bias[col + 1];
#pragma unroll
        for (int mi = 0; mi < 2; ++mi) {
            acc[mi][nj][0] += bx; acc[mi][nj][1] += by;
            acc[mi][nj][2] += bx; acc[mi][nj][3] += by;
        }
    }

    // store h
    float* H = g_h + (size_t)r * (NN * FF) + nh * 64;
#pragma unroll
    for (int mi = 0; mi < 2; ++mi) {
        int ra = row0 + wm + mi * 16 + gq;
#pragma unroll
        for (int nj = 0; nj < 2; ++nj) {
            int col = wn + nj * 8 + 2 * tq;
            if (ra < NN)
                *(float2*)(H + (size_t)ra * FF + col) = make_float2(acc[mi][nj][0], acc[mi][nj][1]);
            if (ra + 8 < NN)
                *(float2*)(H + (size_t)(ra + 8) * FF + col) = make_float2(acc[mi][nj][2], acc[mi][nj][3]);
        }
    }

    // fused BN stats via shuffle reduction (no shared atomics).
    // thread partials per (nj,par) -> reduce over gq lanes (3 shuffles) -> lanes 0-3
    // stage per-warp 16 cols -> final 2-way sum by 64 threads -> 1 global atomic.
    float sv[2][2], qv[2][2];
#pragma unroll
    for (int nj = 0; nj < 2; ++nj)
#pragma unroll
        for (int par = 0; par < 2; ++par) {
            float s = 0.f, q = 0.f;
#pragma unroll
            for (int mi = 0; mi < 2; ++mi) {
                int ra = row0 + wm + mi * 16 + gq;
                if (ra < NN) {
                    float v = acc[mi][nj][par];
                    s += v; q = fmaf(v, v, q);
                }
                if (ra + 8 < NN) {
                    float v = acc[mi][nj][2 + par];
                    s += v; q = fmaf(v, v, q);
                }
            }
            s += __shfl_down_sync(0xffffffffu, s, 16);
            q += __shfl_down_sync(0xffffffffu, q, 16);
            s += __shfl_down_sync(0xffffffffu, s, 8);
            q += __shfl_down_sync(0xffffffffu, q, 8);
            s += __shfl_down_sync(0xffffffffu, s, 4);
            q += __shfl_down_sync(0xffffffffu, q, 4);
            sv[nj][par] = s;
            qv[nj][par] = q;
        }
    __syncthreads();  // done with A/B tiles; reuse smem for staging
    float* reds = (float*)sm;        // [8 warps][16 cols]
    float* redq = (float*)sm + 128;  // [8 warps][16 cols]
    if (lane < 4) {
#pragma unroll
        for (int nj = 0; nj < 2; ++nj)
#pragma unroll
            for (int par = 0; par < 2; ++par) {
                int lc = nj * 8 + 2 * lane + par;
                reds[wid * 16 + lc] = sv[nj][par];
                redq[wid * 16 + lc] = qv[nj][par];
            }
    }
    __syncthreads();
    if (tid < 64) {
        int w0 = (tid >> 4) * 2, lc = tid & 15;
        float s = reds[w0 * 16 + lc] + reds[(w0 + 1) * 16 + lc];
        float q = redq[w0 * 16 + lc] + redq[(w0 + 1) * 16 + lc];
        atomicAdd(&g_sum[r * FF + nh * 64 + tid], s);
        atomicAdd(&g_sumsq[r * FF + nh * 64 + tid], q);
    }
}

// ================= GEMM2: 64x128, 2 CTAs/SM, register A-prefetch ====================
// smem u32: Ah[0,4096) Al[4096,8192) Bh[8192,16384) Bl[16384,24576)
// extras: s_scale[512]@24576, s_shift[512]@25088, s_bias[128]@25600.
#define SMEM2_BYTES 102912

__device__ __forceinline__ void copy_b128_async(uint32_t smb, int mat, int tid) {
    const float4* src = (const float4*)(g_wb + (size_t)mat * 16384u);
    uint32_t dst = smb + 32768u + (uint32_t)tid * 16u;
#pragma unroll
    for (int it = 0; it < 16; ++it) CP16(dst + it * 4096u, src + it * 256 + tid);
}

__device__ __forceinline__ void frag_bases128(uint32_t smb, int lane, int wm, int wn,
                                              uint32_t& arow, uint32_t& brow,
                                              uint32_t& aku0, uint32_t& bku0, uint32_t& sw) {
    arow = smb + (uint32_t)(wm + (lane & 15)) * 256u;
    brow = smb + 32768u + (uint32_t)(wn + (lane & 7)) * 256u;
    aku0 = ((uint32_t)(lane >> 4)) << 2;
    bku0 = (((uint32_t)(lane >> 3)) & 1u) << 2;
    sw = ((uint32_t)(lane & 7)) << 2;
}

__device__ __forceinline__ void mma_tile128(float (*acc)[4][4], uint32_t arow, uint32_t brow,
                                            uint32_t aku0, uint32_t bku0, uint32_t sw) {
#pragma unroll
    for (int kc = 0; kc < 8; ++kc) {
        uint32_t ak = ((aku0 + 8u * kc) ^ sw) << 2;
        uint32_t bk = ((bku0 + 8u * kc) ^ sw) << 2;
        unsigned bh[4][2], bl[4][2];
#pragma unroll
        for (int nj = 0; nj < 4; ++nj) {
            LDSM2(bh[nj], brow + nj * 2048u + bk);
            LDSM2(bl[nj], brow + 32768u + nj * 2048u + bk);
        }
#pragma unroll
        for (int mi = 0; mi < 2; ++mi) {
            unsigned ah[4], al[4];
            LDSM4(ah, arow + mi * 4096u + ak);
            LDSM4(al, arow + 16384u + mi * 4096u + ak);
#pragma unroll
            for (int nj = 0; nj < 4; ++nj) {
                MMA_BF16(acc[mi][nj], ah, bh[nj]);
                MMA_BF16(acc[mi][nj], ah, bl[nj]);
                MMA_BF16(acc[mi][nj], al, bh[nj]);
            }
        }
    }
}

__global__ __launch_bounds__(256, 2) void gemm2_tc(const float* __restrict__ x,
                                                   const float* __restrict__ gamma,
                                                   const float* __restrict__ beta,
                                                   const float* __restrict__ bself,
                                                   const float* __restrict__ b2g,
                                                   float* __restrict__ out) {
    extern __shared__ unsigned sm[];
    unsigned* Ah = sm;
    unsigned* Al = sm + 4096;
    float* s_scale = (float*)(sm + 24576);
    float* s_shift = (float*)(sm + 25088);
    float* s_bias  = (float*)(sm + 25600);
    const uint32_t smb = smem_u32(sm);
    const int tid = threadIdx.x, wid = tid >> 5, lane = tid & 31;
    const int gq = lane >> 2, tq = lane & 3;
    const int wm = (wid & 1) * 32, wn = (wid >> 1) * 32;
    const int row0 = blockIdx.x * 64;

    // fused BN finalize (reads gemm1's global stats)
    for (int i = tid; i < RR * FF; i += 256) {
        float inv_n = 1.0f / (float)NN;
        float mean = g_sum[i] * inv_n;
        float var = g_sumsq[i] * inv_n - mean * mean;
        if (var < 0.f) var = 0.f;
        float scv = gamma[i] * rsqrtf(var + 1e-5f);
        s_scale[i] = scv;
        s_shift[i] = beta[i] - mean * scv;
    }
    for (int i = tid; i < FF; i += 256) {
        float b = bself[i];
#pragma unroll
        for (int rr = 0; rr < RR; ++rr) b += b2g[rr * FF + i];
        s_bias[i] = b;
    }

    float acc[2][4][4];
#pragma unroll
    for (int mi = 0; mi < 2; ++mi)
#pragma unroll
        for (int nj = 0; nj < 4; ++nj)
#pragma unroll
            for (int c = 0; c < 4; ++c) acc[mi][nj][c] = 0.f;

    uint32_t arow, brow, aku0, bku0, sw;
    frag_bases128(smb, lane, wm, wn, arow, brow, aku0, bku0, sw);

    // prefetch rel=0 A (x) into registers
    float4 pre[8];
#pragma unroll
    for (int it = 0; it < 8; ++it) {
        int q = it * 256 + tid;
        int row = q >> 5, c4 = q & 31;
        int grow = row0 + row;
        pre[it] = (grow < NN) ? ((const float4*)x)[(size_t)grow * 32 + c4]
                              : make_float4(0.f, 0.f, 0.f, 0.f);
    }

    for (int rel = 0; rel < 5; ++rel) {
        __syncthreads();  // prev mma done reading smem; BN tables visible (rel>=1)
        copy_b128_async(smb, 4 + rel, tid);

        const float* sc = s_scale + (rel - 1) * FF;
        const float* sf = s_shift + (rel - 1) * FF;
#pragma unroll
        for (int it = 0; it < 8; ++it) {
            int q = it * 256 + tid;
            int row = q >> 5, c4 = q & 31, k4 = c4 * 4;
            float4 v = pre[it];
            if (rel > 0) {
                v.x = fmaxf(fmaf(v.x, sc[k4 + 0], sf[k4 + 0]), 0.f);
                v.y = fmaxf(fmaf(v.y, sc[k4 + 1], sf[k4 + 1]), 0.f);
                v.z = fmaxf(fmaf(v.z, sc[k4 + 2], sf[k4 + 2]), 0.f);
                v.w = fmaxf(fmaf(v.w, sc[k4 + 3], sf[k4 + 3]), 0.f);
            }
            unsigned h0, l0, h1, l1;
            split2(v.x, v.y, h0, l0);
            split2(v.z, v.w, h1, l1);
            int idx = row * 64 + ((c4 * 2) ^ ((row & 7) << 2));
            Ah[idx] = h0; Ah[idx + 1] = h1;
            Al[idx] = l0; Al[idx + 1] = l1;
        }
        CP_WAIT();
        __syncthreads();

        // issue next rel's A loads BEFORE the mma — latency hides behind tensor work
        if (rel < 4) {
            const float* An = g_h + (size_t)rel * (NN * FF);  // rel+1 maps to g_h[rel]
#pragma unroll
            for (int it = 0; it < 8; ++it) {
                int q = it * 256 + tid;
                int row = q >> 5, c4 = q & 31;
                int grow = row0 + row;
                pre[it] = (grow < NN) ? ((const float4*)An)[(size_t)grow * 32 + c4]
                                      : make_float4(0.f, 0.f, 0.f, 0.f);
            }
        }

        mma_tile128(acc, arow, brow, aku0, bku0, sw);
    }

#pragma unroll
    for (int mi = 0; mi < 2; ++mi) {
        int ra = row0 + wm + mi * 16 + gq;
#pragma unroll
        for (int nj = 0; nj < 4; ++nj) {
            int col = wn + nj * 8 + 2 * tq;
            float bx = s_bias[col], by = s_bias[col + 1];
            if (ra < NN)
                *(float2*)(out + (size_t)ra * FF + col) =
                    make_float2(acc[mi][nj][0] + bx, acc[mi][nj][1] + by);
            if (ra + 8 < NN)
                *(float2*)(out + (size_t)(ra + 8) * FF + col) =
                    make_float2(acc[mi][nj][2] + bx, acc[mi][nj][3] + by);
        }
    }
}

// ---------------- launch ---------------------------------------------------------
extern "C" void kernel_launch(void* const* d_in, const int* in_sizes, int n_in,
                              void* d_out, int out_size) {
    const float* x     = (const float*)d_in[0];
    const int*   ei    = (const int*)d_in[1];
    const int*   et    = (const int*)d_in[2];
    const float* Wself = (const float*)d_in[3];
    const float* bself = (const float*)d_in[4];
    const float* W1    = (const float*)d_in[5];
    const float* b1    = (const float*)d_in[6];
    const float* gamma = (const float*)d_in[7];
    const float* beta  = (const float*)d_in[8];
    const float* W2    = (const float*)d_in[9];
    const float* b2    = (const float*)d_in[10];
    float* out = (float*)d_out;

    void* p_cnt = nullptr;
    cudaGetSymbolAddress(&p_cnt, g_cnt);
    cudaMemsetAsync(p_cnt, 0, RN * sizeof(int));

    cudaFuncSetAttribute(gemm1_tc, cudaFuncAttributeMaxDynamicSharedMemorySize, SMEM1_BYTES);
    cudaFuncSetAttribute(gemm2_tc, cudaFuncAttributeMaxDynamicSharedMemorySize, SMEM2_BYTES);

    prep_hist_kernel<<<9 + (EE + 255) / 256, 256>>>(W1, Wself, W2, ei, et);   // 1
    scan1_kernel<<<NBLK, 512>>>();                                            // 2
    reorder_kernel<<<(EE + 255) / 256, 256>>>(ei, et);                        // 3
    gather_kernel<<<(RR * ROWS * 32) / 256, 256>>>((const float4*)x);         // 4: profiled
    gemm1_tc<<<dim3(NT, 2 * RR), 256, SMEM1_BYTES>>>(b1);                     // 5
    gemm2_tc<<<NT, 256, SMEM2_BYTES>>>(x, gamma, beta, bself, b2, out);       // 6
}